// round 1
// baseline (speedup 1.0000x reference)
#include <cuda_runtime.h>
#include <math_constants.h>

#define FH 64
#define FW 64
#define FC 128
#define NB 2
#define NROI 256
#define OH 7
#define OW 7
#define SCALE 0.0625f

// NHWC scratch: [b][y][x][c], 2*64*64*128 floats = 4 MB (device global, no alloc)
__device__ float g_feat_t[NB * FH * FW * FC];

// NCHW -> NHWC transpose. tid enumerates NHWC order (c fastest) so the WRITE
// is fully coalesced; reads are 32-way strided but the whole tensor is 4 MB
// and L2-resident, so this is cheap.
__global__ void transpose_nchw_nhwc(const float* __restrict__ feat) {
    int tid = blockIdx.x * blockDim.x + threadIdx.x;
    int c = tid & (FC - 1);
    int x = (tid >> 7) & (FW - 1);
    int y = (tid >> 13) & (FH - 1);
    int b = tid >> 19;
    g_feat_t[tid] = feat[((b * FC + c) * FH + y) * FW + x];
}

// One warp per (roi, ph, pw) bin. Lane l owns channels [4l, 4l+4) as float4.
// Each region pixel = one warp-wide coalesced 512B load of all 128 channels.
__global__ void roipool_kernel(const float* __restrict__ rois,
                               float* __restrict__ out) {
    int gtid = blockIdx.x * blockDim.x + threadIdx.x;
    int wg   = gtid >> 5;            // global warp id
    int lane = threadIdx.x & 31;
    if (wg >= NROI * OH * OW) return;

    int r   = wg / (OH * OW);
    int bin = wg - r * (OH * OW);
    int ph  = bin / OW;
    int pw  = bin - ph * OW;

    // ROI decode (all lanes redundantly; L1-broadcast hits)
    const float* rp = rois + r * 5;
    int b  = (int)rp[0];
    int x1 = (int)(rp[1] * SCALE);
    int y1 = (int)(rp[2] * SCALE);
    int x2 = (int)(rp[3] * SCALE);
    int y2 = (int)(rp[4] * SCALE);
    int h = y2 - y1;
    int w = x2 - x1;

    int hs = y1 + (ph * h) / OH;
    int he = y1 + ((ph + 1) * h + OH - 1) / OH;
    int ws = x1 + (pw * w) / OW;
    int we = x1 + ((pw + 1) * w + OW - 1) / OW;

    float4 acc = make_float4(-CUDART_INF_F, -CUDART_INF_F,
                             -CUDART_INF_F, -CUDART_INF_F);

    const float4* t4 = reinterpret_cast<const float4*>(g_feat_t);
    const int C4 = FC / 4;  // 32 float4 per pixel

    for (int y = hs; y < he; ++y) {
        // float4 index of pixel (b, y, ws): ((b*FH + y)*FW + x)*C4 + lane
        const float4* rowp = t4 + ((size_t)(b * FH + y) * FW) * C4 + lane;
        #pragma unroll 4
        for (int x = ws; x < we; ++x) {
            float4 v = rowp[(size_t)x * C4];
            acc.x = fmaxf(acc.x, v.x);
            acc.y = fmaxf(acc.y, v.y);
            acc.z = fmaxf(acc.z, v.z);
            acc.w = fmaxf(acc.w, v.w);
        }
    }

    if (h <= 0 || w <= 0) {   // empty ROI -> reference maps -inf to 0
        acc = make_float4(0.f, 0.f, 0.f, 0.f);
    }

    // out[r][c][ph][pw], c = 4*lane + k ; stride between channels = 49
    int cbase = lane * 4;
    float* op = out + ((size_t)r * FC + cbase) * (OH * OW) + bin;
    op[0 * OH * OW] = acc.x;
    op[1 * OH * OW] = acc.y;
    op[2 * OH * OW] = acc.z;
    op[3 * OH * OW] = acc.w;
}

extern "C" void kernel_launch(void* const* d_in, const int* in_sizes, int n_in,
                              void* d_out, int out_size) {
    const float* feat = (const float*)d_in[0];   // (2,128,64,64) fp32
    const float* rois = (const float*)d_in[1];   // (256,5) fp32
    float* out = (float*)d_out;                  // (256,128,7,7) fp32

    // Kernel 1: NCHW -> NHWC (4 MB)
    int total = NB * FC * FH * FW;               // 2,097,152
    transpose_nchw_nhwc<<<total / 256, 256>>>(feat);

    // Kernel 2: one warp per (roi, bin): 256*49 = 12544 warps, 8 warps/block
    int nwarps = NROI * OH * OW;
    int nblocks = (nwarps * 32 + 255) / 256;     // 1568
    roipool_kernel<<<nblocks, 256>>>(rois, out);
}

// round 2
// speedup vs baseline: 1.1103x; 1.1103x over previous
#include <cuda_runtime.h>
#include <math_constants.h>

#define FH 64
#define FW 64
#define FC 128
#define NB 2
#define NROI 256
#define OH 7
#define OW 7
#define NBIN (OH * OW)          // 49
#define SCALE 0.0625f
#define C4 (FC / 4)             // 32 float4 per pixel

// NHWC scratch: [b][y][x][c], 2*64*64*128 floats = 4 MB (device global, no alloc)
__device__ float g_feat_t[NB * FH * FW * FC];

// ---------------------------------------------------------------------------
// Kernel 1: NCHW -> NHWC via smem tile. One block per (b, y) row.
// Load: coalesced along x (contiguous per channel). Store: coalesced along c.
// smem tile padded to 65 floats/row -> both phases bank-conflict-free.
// ---------------------------------------------------------------------------
__global__ __launch_bounds__(256) void transpose_nchw_nhwc(const float* __restrict__ feat) {
    __shared__ float s[FC][FW + 1];          // 128 x 65 floats = 33.3 KB
    int row = blockIdx.x;                    // 0..127 : b*64 + y
    int b = row >> 6;
    int y = row & 63;

    // feat[b][c][y][x] ; stride between channels = FH*FW
    const float* src = feat + ((size_t)b * FC * FH + y) * FW;
    for (int idx = threadIdx.x; idx < FC * FW; idx += 256) {
        int c = idx >> 6;                    // 0..127
        int x = idx & 63;
        s[c][x] = src[(size_t)c * FH * FW + x];   // warp: 2x256B contiguous reads
    }
    __syncthreads();

    // g_feat_t[b][y][x][c], c fastest -> contiguous 8192-float write
    float* dst = g_feat_t + (size_t)row * FW * FC;
    for (int idx = threadIdx.x; idx < FC * FW; idx += 256) {
        int c = idx & 127;                   // lanes -> consecutive c -> banks c%32
        int x = idx >> 7;
        dst[idx] = s[c][x];                  // coalesced STG.32
    }
}

// ---------------------------------------------------------------------------
// Kernel 2: one block (512 thr = 16 warps) per ROI.
// Warp w handles bins {w, w+16, w+32} (+bin 48 for warp 0); lane l owns
// channels [4l,4l+4) as float4 -> each region pixel is one coalesced 512B
// warp load. Dual-row streaming for MLP. Results staged in smem, then the
// ROI's 6272 contiguous output floats are written as coalesced float4.
// ---------------------------------------------------------------------------
__global__ __launch_bounds__(512) void roipool_kernel(const float* __restrict__ rois,
                                                      float* __restrict__ out) {
    __shared__ float s_out[FC * NBIN];       // [c][bin] flat = 25088 B

    int r    = blockIdx.x;
    int wid  = threadIdx.x >> 5;
    int lane = threadIdx.x & 31;

    const float* rp = rois + r * 5;
    int b  = (int)rp[0];
    int x1 = (int)(rp[1] * SCALE);
    int y1 = (int)(rp[2] * SCALE);
    int x2 = (int)(rp[3] * SCALE);
    int y2 = (int)(rp[4] * SCALE);
    int h = y2 - y1;
    int w = x2 - x1;
    bool empty = (h <= 0) || (w <= 0);

    const float4* bbase = reinterpret_cast<const float4*>(g_feat_t)
                        + ((size_t)b * FH * FW) * C4 + lane;

    for (int bin = wid; bin < NBIN; bin += 16) {
        int ph = bin / OW;
        int pw = bin - ph * OW;

        int hs = y1 + (ph * h) / OH;
        int he = y1 + ((ph + 1) * h + OH - 1) / OH;
        int ws = x1 + (pw * w) / OW;
        int we = x1 + ((pw + 1) * w + OW - 1) / OW;

        float4 a0 = make_float4(-CUDART_INF_F, -CUDART_INF_F,
                                -CUDART_INF_F, -CUDART_INF_F);
        float4 a1 = a0;

        int y = hs;
        for (; y + 1 < he; y += 2) {         // two independent load streams
            const float4* r0 = bbase + (size_t)(y * FW) * C4;
            const float4* r1 = r0 + (size_t)FW * C4;
            #pragma unroll 4
            for (int x = ws; x < we; ++x) {
                float4 v0 = r0[(size_t)x * C4];
                float4 v1 = r1[(size_t)x * C4];
                a0.x = fmaxf(a0.x, v0.x); a0.y = fmaxf(a0.y, v0.y);
                a0.z = fmaxf(a0.z, v0.z); a0.w = fmaxf(a0.w, v0.w);
                a1.x = fmaxf(a1.x, v1.x); a1.y = fmaxf(a1.y, v1.y);
                a1.z = fmaxf(a1.z, v1.z); a1.w = fmaxf(a1.w, v1.w);
            }
        }
        if (y < he) {                        // remainder row
            const float4* r0 = bbase + (size_t)(y * FW) * C4;
            #pragma unroll 4
            for (int x = ws; x < we; ++x) {
                float4 v0 = r0[(size_t)x * C4];
                a0.x = fmaxf(a0.x, v0.x); a0.y = fmaxf(a0.y, v0.y);
                a0.z = fmaxf(a0.z, v0.z); a0.w = fmaxf(a0.w, v0.w);
            }
        }
        a0.x = fmaxf(a0.x, a1.x); a0.y = fmaxf(a0.y, a1.y);
        a0.z = fmaxf(a0.z, a1.z); a0.w = fmaxf(a0.w, a1.w);

        if (empty) a0 = make_float4(0.f, 0.f, 0.f, 0.f);

        float* sp = s_out + bin;             // s_out[c*49 + bin]
        int cb = lane * 4;
        sp[(cb + 0) * NBIN] = a0.x;
        sp[(cb + 1) * NBIN] = a0.y;
        sp[(cb + 2) * NBIN] = a0.z;
        sp[(cb + 3) * NBIN] = a0.w;
    }
    __syncthreads();

    // Coalesced epilogue: 6272 floats = 1568 float4, contiguous in gmem.
    const float4* s4 = reinterpret_cast<const float4*>(s_out);
    float4* o4 = reinterpret_cast<float4*>(out + (size_t)r * FC * NBIN);
    for (int i = threadIdx.x; i < (FC * NBIN) / 4; i += 512)
        o4[i] = s4[i];
}

extern "C" void kernel_launch(void* const* d_in, const int* in_sizes, int n_in,
                              void* d_out, int out_size) {
    const float* feat = (const float*)d_in[0];   // (2,128,64,64) fp32
    const float* rois = (const float*)d_in[1];   // (256,5) fp32
    float* out = (float*)d_out;                  // (256,128,7,7) fp32

    transpose_nchw_nhwc<<<NB * FH, 256>>>(feat);
    roipool_kernel<<<NROI, 512>>>(rois, out);
}